// round 14
// baseline (speedup 1.0000x reference)
#include <cuda_runtime.h>
#include <cuda_fp16.h>
#include <cstdint>

#define DEV_INLINE __device__ __forceinline__

// ---------------------------------------------------------------------------
// Problem constants: B=4, T=2048, E=2048, H=16, KV=4, G=4, D=128
// Fused QKV width: H*D + 2*KV*D = 3072
// ---------------------------------------------------------------------------

// Scratch (device-global: allocation-free per harness rules)
__device__ __half g_xh  [4 * 2048 * 2048];     // x half             32 MB
__device__ __half g_Wf  [3072 * 2048];         // [Wq;Wk;Wv]^T half  12 MB
__device__ __half g_Wot [2048 * 2048];         // Wo^T half           8 MB
__device__ __half g_QKV [4 * 2048 * 3072];     // fused QKV out      48 MB
__device__ __half g_Vt  [4 * 4 * 128 * 2048];  // (B,KV,D,T)          8 MB
__device__ __half g_AYh [4 * 2048 * 2048];     // attn out half      32 MB

DEV_INLINE uint32_t packh2(float lo, float hi) {
    __half2 h = __floats2half2_rn(lo, hi);
    return *reinterpret_cast<uint32_t*>(&h);
}
DEV_INLINE void mma16(float* c, const uint32_t* a, const uint32_t* b) {
    asm("mma.sync.aligned.m16n8k16.row.col.f32.f16.f16.f32 "
        "{%0,%1,%2,%3}, {%4,%5,%6,%7}, {%8,%9}, {%0,%1,%2,%3};"
        : "+f"(c[0]), "+f"(c[1]), "+f"(c[2]), "+f"(c[3])
        : "r"(a[0]), "r"(a[1]), "r"(a[2]), "r"(a[3]), "r"(b[0]), "r"(b[1]));
}
DEV_INLINE uint32_t sptr(const void* p) {
    return (uint32_t)__cvta_generic_to_shared(p);
}
DEV_INLINE void cp16(uint32_t dst, const void* src) {
    asm volatile("cp.async.cg.shared.global [%0], [%1], 16;" ::
                     "r"(dst), "l"(src));
}
DEV_INLINE void ldsm4(uint32_t* r, uint32_t addr) {
    asm volatile("ldmatrix.sync.aligned.m8n8.x4.shared.b16 {%0,%1,%2,%3}, [%4];"
                 : "=r"(r[0]), "=r"(r[1]), "=r"(r[2]), "=r"(r[3])
                 : "r"(addr));
}

// ---------------------------------------------------------------------------
// Prep kernels
// ---------------------------------------------------------------------------
__global__ __launch_bounds__(256) void f2h_kernel(const float* __restrict__ in,
                                                  __half* __restrict__ out) {
    int i = (blockIdx.x * 256 + threadIdx.x) * 4;
    float4 v = *(const float4*)(in + i);
    uint2 o;
    o.x = packh2(v.x, v.y);
    o.y = packh2(v.z, v.w);
    *(uint2*)(out + i) = o;
}

// Fused weight transpose: all four W (K=2048, N) f32 -> (N, 2048) half.
// grid (160, 64): bx<64 Wq | <80 Wk | <96 Wv | else Wo. Tile 32x32.
__global__ __launch_bounds__(256) void transpose_w4(
    const float* __restrict__ Wq, const float* __restrict__ Wk,
    const float* __restrict__ Wv, const float* __restrict__ Wo,
    __half* __restrict__ Wf, __half* __restrict__ Wot) {
    __shared__ float t[32][33];
    const int bx = blockIdx.x;
    const float* W;
    __half* Wt;
    int Ncols, n0;
    if (bx < 64) {
        W = Wq; Wt = Wf; Ncols = 2048; n0 = bx * 32;
    } else if (bx < 80) {
        W = Wk; Wt = Wf + (size_t)2048 * 2048; Ncols = 512; n0 = (bx - 64) * 32;
    } else if (bx < 96) {
        W = Wv; Wt = Wf + (size_t)2560 * 2048; Ncols = 512; n0 = (bx - 80) * 32;
    } else {
        W = Wo; Wt = Wot; Ncols = 2048; n0 = (bx - 96) * 32;
    }
    const int k0 = blockIdx.y * 32;
    const int lx = threadIdx.x & 31, ly = threadIdx.x >> 5;
#pragma unroll
    for (int i = 0; i < 4; i++)
        t[ly + 8 * i][lx] = W[(size_t)(k0 + ly + 8 * i) * Ncols + n0 + lx];
    __syncthreads();
#pragma unroll
    for (int i = 0; i < 4; i++)
        Wt[(size_t)(n0 + ly + 8 * i) * 2048 + k0 + lx] =
            __float2half(t[lx][ly + 8 * i]);
}

// ---------------------------------------------------------------------------
// fp16 GEMM: C(MxN) = A(M,K) @ Bt(N,K)^T.
// BM=128 BN=128 BK=32; 256 threads = 8 warps (2m x 4n); warp tile 64x32.
// 5-stage cp.async pipeline (4 tiles in flight), one barrier per iteration,
// ldmatrix fragments. smem rows 20 uint32 (80 B): conflict-free phases.
// ---------------------------------------------------------------------------
template <int N, bool HALF_OUT>
__global__ __launch_bounds__(256) void gemm_hh(const __half* __restrict__ A,
                                               const __half* __restrict__ Bt,
                                               void* __restrict__ Cv) {
    constexpr int K = 2048;
    constexpr int NT = K / 32;
    constexpr int STG = 128 * 20;  // uint32 units per stage per operand
    extern __shared__ uint32_t smem[];

    const int tid = threadIdx.x;
    const int lane = tid & 31, wid = tid >> 5;
    const int g = lane >> 2, t = lane & 3;
    const int wm = wid & 1, wn = wid >> 1;
    const int bm = blockIdx.y * 128, bn = blockIdx.x * 128;

    const int l_row = tid >> 1;       // 0..127
    const int l_u0  = (tid & 1) * 8;  // unit 0 or 8

    const __half* gA = A + (size_t)(bm + l_row) * K + 2 * l_u0;
    const __half* gB = Bt + (size_t)(bn + l_row) * K + 2 * l_u0;

    const uint32_t sA = sptr(smem);
    const uint32_t sB = sA + 5 * STG * 4;
    const uint32_t stA = sA + l_row * 80 + l_u0 * 4;
    const uint32_t stB = sB + l_row * 80 + l_u0 * 4;

    const uint32_t aAddr =
        sA + (wm * 64 + (lane & 7) + ((lane >> 3) & 1) * 8) * 80 +
        ((lane >> 4) * 4) * 4;
    const uint32_t bAddr =
        sB + (wn * 32 + (lane & 7) + ((lane >> 4) & 1) * 8) * 80 +
        (((lane >> 3) & 1) * 4) * 4;

    float acc[4][4][4];
#pragma unroll
    for (int mi = 0; mi < 4; mi++)
#pragma unroll
        for (int ni = 0; ni < 4; ni++)
#pragma unroll
            for (int j = 0; j < 4; j++) acc[mi][ni][j] = 0.f;

    auto issue = [&](int kt) {
        const uint32_t off = (kt % 5) * STG * 4;
        const __half* a = gA + kt * 32;
        cp16(stA + off, a);
        cp16(stA + off + 16, a + 8);
        const __half* b = gB + kt * 32;
        cp16(stB + off, b);
        cp16(stB + off + 16, b + 8);
        asm volatile("cp.async.commit_group;" ::: "memory");
    };

    issue(0);
    issue(1);
    issue(2);
    issue(3);

    for (int kt = 0; kt < NT; kt++) {
        if (kt < NT - 3)
            asm volatile("cp.async.wait_group 3;" ::: "memory");
        else if (kt == NT - 3)
            asm volatile("cp.async.wait_group 2;" ::: "memory");
        else if (kt == NT - 2)
            asm volatile("cp.async.wait_group 1;" ::: "memory");
        else
            asm volatile("cp.async.wait_group 0;" ::: "memory");
        __syncthreads();
        if (kt + 4 < NT) issue(kt + 4);

        const uint32_t soff = (kt % 5) * STG * 4;
#pragma unroll
        for (int ks = 0; ks < 2; ks++) {
            uint32_t aF[4][4], bF[2][4];
#pragma unroll
            for (int mi = 0; mi < 4; mi++)
                ldsm4(aF[mi], aAddr + soff + mi * 16 * 80 + ks * 32);
            ldsm4(bF[0], bAddr + soff + ks * 32);
            ldsm4(bF[1], bAddr + soff + 16 * 80 + ks * 32);
#pragma unroll
            for (int ni = 0; ni < 4; ni++) {
                const uint32_t* bp = &bF[ni >> 1][(ni & 1) * 2];
#pragma unroll
                for (int mi = 0; mi < 4; mi++) mma16(acc[mi][ni], aF[mi], bp);
            }
        }
    }

    // epilogue
#pragma unroll
    for (int mi = 0; mi < 4; mi++) {
        int r0 = bm + wm * 64 + mi * 16 + g;
#pragma unroll
        for (int ni = 0; ni < 4; ni++) {
            int cN = bn + wn * 32 + ni * 8 + 2 * t;
            if (HALF_OUT) {
                __half* C = (__half*)Cv;
                *reinterpret_cast<__half2*>(C + (size_t)r0 * N + cN) =
                    __floats2half2_rn(acc[mi][ni][0], acc[mi][ni][1]);
                *reinterpret_cast<__half2*>(C + (size_t)(r0 + 8) * N + cN) =
                    __floats2half2_rn(acc[mi][ni][2], acc[mi][ni][3]);
            } else {
                float* C = (float*)Cv;
                *(float2*)(C + (size_t)r0 * N + cN) =
                    make_float2(acc[mi][ni][0], acc[mi][ni][1]);
                *(float2*)(C + (size_t)(r0 + 8) * N + cN) =
                    make_float2(acc[mi][ni][2], acc[mi][ni][3]);
            }
        }
    }
}

// ---------------------------------------------------------------------------
// V transpose: V slice of fused QKV (row stride 3072) -> g_Vt (B,KV,D,T),
// key-pair packed half2.
// ---------------------------------------------------------------------------
__global__ __launch_bounds__(256) void transpose_v(const __half* __restrict__ C,
                                                   __half* __restrict__ Vt) {
    __shared__ uint32_t U[64][33];
    const int tid = threadIdx.x;
    const int k0 = blockIdx.x * 64;
    const int kv = blockIdx.y >> 1;
    const int d0 = (blockIdx.y & 1) * 64;
    const int b  = blockIdx.z;

    const uint32_t* in = reinterpret_cast<const uint32_t*>(C);
    {
        int dp = tid & 31;
        int krow = tid >> 5;
#pragma unroll
        for (int i = 0; i < 8; i++) {
            int key = i * 8 + krow;
            U[key][dp] = in[(size_t)(b * 2048 + k0 + key) * 1536 + 1280 +
                            kv * 64 + (d0 >> 1) + dp];
        }
    }
    __syncthreads();
    uint32_t* out = reinterpret_cast<uint32_t*>(Vt);
    {
        int kp = tid & 31;
        int drow = tid >> 5;
#pragma unroll
        for (int i = 0; i < 8; i++) {
            int d = i * 8 + drow;
            uint32_t a = U[2 * kp][d >> 1];
            uint32_t c = U[2 * kp + 1][d >> 1];
            uint32_t lo = (d & 1) ? (a >> 16) : (a & 0xffffu);
            uint32_t hi = (d & 1) ? (c >> 16) : (c & 0xffffu);
            out[(size_t)((b * 4 + kv) * 128 + d0 + d) * 1024 + (k0 >> 1) + kp] =
                lo | (hi << 16);
        }
    }
}

// ---------------------------------------------------------------------------
// Flash attention (causal, GQA), fp16 m16n8k16 core, f32 softmax/accum.
// NEW: 128-query CTAs. Grid (T/128, H, B), 256 threads = 8 warps; each warp
// owns 16 query rows. K/V tiles (32 keys) serve all 128 queries -> per-query
// load and barrier cost halved vs 64-query CTAs. Double-buffered cp.async.
// Dynamic smem 82944 B (2 CTAs/SM). Numerics identical per query row.
//
// Smem layout (uint32 units from base):
//   Qs : [0, 8704)        128 rows x 68   (272 B rows)
//   Ks : [8704, +4352)    2 bufs x 32 x 68
//   Vs : [13056, +5120)   2 bufs x 128 x 20 (80 B rows)
//   Ps : [18176, +2560)   8 warps x 16 x 20
// ---------------------------------------------------------------------------
static constexpr int QS_U = 0;
static constexpr int KS_U = 8704;
static constexpr int KS_STG = 2176;  // 32*68
static constexpr int VS_U = 13056;
static constexpr int VS_STG = 2560;  // 128*20
static constexpr int PS_U = 18176;
static constexpr int ATTN_SMEM = 20736 * 4;  // 82944 B

__global__ __launch_bounds__(256) void attn_f16(const __half* __restrict__ Cqkv,
                                                const __half* __restrict__ Vt,
                                                __half* __restrict__ Y) {
    extern __shared__ uint32_t dsm[];

    const int b = blockIdx.z, h = blockIdx.y, qb = blockIdx.x;
    const int kv = h >> 2;
    const int tid = threadIdx.x, w = tid >> 5, lane = tid & 31;
    const int g = lane >> 2, t = lane & 3;
    const float scale = 0.08838834764831845f;

    const uint4* Cv = reinterpret_cast<const uint4*>(Cqkv);
    const uint32_t smb = sptr(dsm);

    const uint32_t qAddr =
        smb + QS_U * 4 +
        (w * 16 + (lane & 7) + ((lane >> 3) & 1) * 8) * 272 +
        ((lane >> 4) * 4) * 4;
    const uint32_t kAddr0 =
        smb + KS_U * 4 + ((lane & 7) + ((lane >> 4) & 1) * 8) * 272 +
        (((lane >> 3) & 1) * 4) * 4;
    const uint32_t vAddr0 =
        smb + VS_U * 4 + ((lane & 7) + ((lane >> 4) & 1) * 8) * 80 +
        (((lane >> 3) & 1) * 4) * 4;
    const uint32_t pAddr =
        smb + (PS_U + w * 320) * 4 + ((lane & 7) + ((lane >> 3) & 1) * 8) * 80 +
        ((lane >> 4) * 4) * 4;

    // cp.async loader mapping (256 threads)
    const int kr = tid >> 3, kc = tid & 7;  // K: 32 rows x 8 col-groups(32B)
    const uint32_t kDst = smb + KS_U * 4 + kr * 272 + kc * 32;
    const __half* kSrc0 =
        Cqkv + (size_t)(b * 2048 + kr) * 3072 + 2048 + kv * 128 + kc * 16;
    const int vr = tid >> 1, vc = tid & 1;  // V: 128 d-rows x 2 groups(32B)
    const uint32_t vDst = smb + VS_U * 4 + vr * 80 + vc * 32;
    const __half* vSrc0 =
        Vt + (size_t)((b * 4 + kv) * 128 + vr) * 2048 + vc * 16;

    // Stage Q block: 128 rows x 16 uint4 (row stride 3072 half = 384 uint4)
    {
        int r = tid >> 1, q = tid & 1;
        size_t base = (size_t)(b * 2048 + qb * 128 + r) * 384 + h * 16;
#pragma unroll
        for (int j = 0; j < 8; j++) {
            uint4 v = Cv[base + q * 8 + j];
            *(uint4*)&dsm[QS_U + r * 68 + (q * 8 + j) * 4] = v;
        }
    }

    const int ntiles = qb * 4 + 4;  // keys 0 .. qb*128+127

    auto issue = [&](int jt) {
        const uint32_t kOff = (jt & 1) * KS_STG * 4;
        const uint32_t vOff = (jt & 1) * VS_STG * 4;
        const __half* ks = kSrc0 + (size_t)(jt * 32) * 3072;
        cp16(kDst + kOff, ks);
        cp16(kDst + kOff + 16, ks + 8);
        const __half* vs = vSrc0 + jt * 32;
        cp16(vDst + vOff, vs);
        cp16(vDst + vOff + 16, vs + 8);
        asm volatile("cp.async.commit_group;" ::: "memory");
    };

    issue(0);
    __syncthreads();  // Q staged + all threads here

    uint32_t qF[8][4];
#pragma unroll
    for (int ks = 0; ks < 8; ks++) ldsm4(qF[ks], qAddr + ks * 32);

    float O[16][4];
#pragma unroll
    for (int i = 0; i < 16; i++)
#pragma unroll
        for (int j = 0; j < 4; j++) O[i][j] = 0.f;
    float m0 = -1e30f, m1 = -1e30f, l0 = 0.f, l1 = 0.f;

    const int qr0 = qb * 128 + w * 16 + g;
    const int qr1 = qr0 + 8;
    const int qmaxw = qb * 128 + w * 16 + 15;

    for (int jt = 0; jt < ntiles; jt++) {
        const int jbase = jt * 32;
        if (jt + 1 < ntiles) issue(jt + 1);
        if (jt + 1 < ntiles)
            asm volatile("cp.async.wait_group 1;" ::: "memory");
        else
            asm volatile("cp.async.wait_group 0;" ::: "memory");
        __syncthreads();  // tile jt visible to all warps

        if (jbase <= qmaxw) {
            const uint32_t kAddr = kAddr0 + (jt & 1) * KS_STG * 4;
            const uint32_t vAddr = vAddr0 + (jt & 1) * VS_STG * 4;

            // S = Q @ K^T  (16 x 32), 8 k16-steps
            float s[4][4];
#pragma unroll
            for (int ni = 0; ni < 4; ni++)
#pragma unroll
                for (int j = 0; j < 4; j++) s[ni][j] = 0.f;
#pragma unroll
            for (int ks = 0; ks < 8; ks++) {
                uint32_t kA[4], kB[4];
                ldsm4(kA, kAddr + ks * 32);
                ldsm4(kB, kAddr + 16 * 272 + ks * 32);
                mma16(s[0], qF[ks], kA);
                mma16(s[1], qF[ks], kA + 2);
                mma16(s[2], qF[ks], kB);
                mma16(s[3], qF[ks], kB + 2);
            }

            // scale + causal mask
#pragma unroll
            for (int ni = 0; ni < 4; ni++) {
                int col = jbase + ni * 8 + 2 * t;
                s[ni][0] = (col     <= qr0) ? s[ni][0] * scale : -1e30f;
                s[ni][1] = (col + 1 <= qr0) ? s[ni][1] * scale : -1e30f;
                s[ni][2] = (col     <= qr1) ? s[ni][2] * scale : -1e30f;
                s[ni][3] = (col + 1 <= qr1) ? s[ni][3] * scale : -1e30f;
            }

            // online softmax row statistics
            float tm0 = -1e30f, tm1 = -1e30f;
#pragma unroll
            for (int ni = 0; ni < 4; ni++) {
                tm0 = fmaxf(tm0, fmaxf(s[ni][0], s[ni][1]));
                tm1 = fmaxf(tm1, fmaxf(s[ni][2], s[ni][3]));
            }
            tm0 = fmaxf(tm0, __shfl_xor_sync(0xffffffffu, tm0, 1));
            tm0 = fmaxf(tm0, __shfl_xor_sync(0xffffffffu, tm0, 2));
            tm1 = fmaxf(tm1, __shfl_xor_sync(0xffffffffu, tm1, 1));
            tm1 = fmaxf(tm1, __shfl_xor_sync(0xffffffffu, tm1, 2));
            float nm0 = fmaxf(m0, tm0), nm1 = fmaxf(m1, tm1);
            float corr0 = __expf(m0 - nm0), corr1 = __expf(m1 - nm1);

            float ls0 = 0.f, ls1 = 0.f;
#pragma unroll
            for (int ni = 0; ni < 4; ni++) {
                s[ni][0] = __expf(s[ni][0] - nm0);
                s[ni][1] = __expf(s[ni][1] - nm0);
                s[ni][2] = __expf(s[ni][2] - nm1);
                s[ni][3] = __expf(s[ni][3] - nm1);
                ls0 += s[ni][0] + s[ni][1];
                ls1 += s[ni][2] + s[ni][3];
            }
            ls0 += __shfl_xor_sync(0xffffffffu, ls0, 1);
            ls0 += __shfl_xor_sync(0xffffffffu, ls0, 2);
            ls1 += __shfl_xor_sync(0xffffffffu, ls1, 1);
            ls1 += __shfl_xor_sync(0xffffffffu, ls1, 2);
            l0 = l0 * corr0 + ls0;
            l1 = l1 * corr1 + ls1;
            m0 = nm0;
            m1 = nm1;

            // rescale O accumulator
#pragma unroll
            for (int nf = 0; nf < 16; nf++) {
                O[nf][0] *= corr0; O[nf][1] *= corr0;
                O[nf][2] *= corr1; O[nf][3] *= corr1;
            }

            // P (C-layout) -> per-warp smem (half2 key-pairs) -> A-frags
#pragma unroll
            for (int ni = 0; ni < 4; ni++) {
                dsm[PS_U + w * 320 + g * 20 + ni * 4 + t] =
                    packh2(s[ni][0], s[ni][1]);
                dsm[PS_U + w * 320 + (g + 8) * 20 + ni * 4 + t] =
                    packh2(s[ni][2], s[ni][3]);
            }
            __syncwarp();

            // O += P @ V   (16x32 @ 32x128), 2 k16-steps
#pragma unroll
            for (int ks2 = 0; ks2 < 2; ks2++) {
                uint32_t aP[4];
                ldsm4(aP, pAddr + ks2 * 32);
#pragma unroll
                for (int nj = 0; nj < 8; nj++) {
                    uint32_t vF[4];
                    ldsm4(vF, vAddr + nj * 16 * 80 + ks2 * 32);
                    mma16(O[nj * 2], aP, vF);
                    mma16(O[nj * 2 + 1], aP, vF + 2);
                }
            }
        }
        __syncthreads();  // all warps done with buffer jt&1 before overwrite
    }

    // epilogue: normalize and store half (feeds half out-projection)
    __half* Yb = Y + ((size_t)(b * 2048 + qb * 128)) * 2048 + h * 128;
    float inv0 = 1.f / l0, inv1 = 1.f / l1;
#pragma unroll
    for (int nf = 0; nf < 16; nf++) {
        int cN = nf * 8 + 2 * t;
        *reinterpret_cast<__half2*>(Yb + (size_t)(w * 16 + g) * 2048 + cN) =
            __floats2half2_rn(O[nf][0] * inv0, O[nf][1] * inv0);
        *reinterpret_cast<__half2*>(Yb + (size_t)(w * 16 + g + 8) * 2048 + cN) =
            __floats2half2_rn(O[nf][2] * inv1, O[nf][3] * inv1);
    }
}

// ---------------------------------------------------------------------------
// Launch
// ---------------------------------------------------------------------------
extern "C" void kernel_launch(void* const* d_in, const int* in_sizes, int n_in,
                              void* d_out, int out_size) {
    (void)in_sizes; (void)n_in; (void)out_size;
    const float* x  = (const float*)d_in[0];
    const float* Wq = (const float*)d_in[1];
    const float* Wk = (const float*)d_in[2];
    const float* Wv = (const float*)d_in[3];
    const float* Wo = (const float*)d_in[4];
    float* out = (float*)d_out;

    __half *xh, *Wf, *Wot, *Cqkv, *Vtp, *AYp;
    cudaGetSymbolAddress((void**)&xh,   g_xh);
    cudaGetSymbolAddress((void**)&Wf,   g_Wf);
    cudaGetSymbolAddress((void**)&Wot,  g_Wot);
    cudaGetSymbolAddress((void**)&Cqkv, g_QKV);
    cudaGetSymbolAddress((void**)&Vtp,  g_Vt);
    cudaGetSymbolAddress((void**)&AYp,  g_AYh);

    const int SMEM_GEMM = 10 * 128 * 20 * 4;  // 102400 B (5 stages x A,B)
    cudaFuncSetAttribute(gemm_hh<3072, true>,
                         cudaFuncAttributeMaxDynamicSharedMemorySize, SMEM_GEMM);
    cudaFuncSetAttribute(gemm_hh<2048, false>,
                         cudaFuncAttributeMaxDynamicSharedMemorySize, SMEM_GEMM);
    cudaFuncSetAttribute(attn_f16,
                         cudaFuncAttributeMaxDynamicSharedMemorySize, ATTN_SMEM);

    // Stage 0: prep (x -> half; all 4 weights -> transposed half, one launch)
    f2h_kernel<<<4 * 2048 * 2048 / 1024, 256>>>(x, xh);
    transpose_w4<<<dim3(160, 64), 256>>>(Wq, Wk, Wv, Wo, Wf, Wot);

    // Stage 1: fused QKV projection (M=8192, N=3072, K=2048)
    gemm_hh<3072, true><<<dim3(24, 64), 256, SMEM_GEMM>>>(xh, Wf, Cqkv);

    // Stage 1b: transpose V slice into (B,KV,D,T) key-pair-packed layout
    transpose_v<<<dim3(32, 8, 4), 256>>>(Cqkv, Vtp);

    // Stage 2: causal GQA flash attention (128-query CTAs, 8 warps)
    attn_f16<<<dim3(16, 16, 4), 256, ATTN_SMEM>>>(Cqkv, Vtp, AYp);

    // Stage 3: output projection (M=8192, N=2048), f32 out
    gemm_hh<2048, false><<<dim3(16, 64), 256, SMEM_GEMM>>>(AYp, Wot, out);
}

// round 15
// speedup vs baseline: 1.0406x; 1.0406x over previous
#include <cuda_runtime.h>
#include <cuda_fp16.h>
#include <cstdint>

#define DEV_INLINE __device__ __forceinline__

// ---------------------------------------------------------------------------
// Problem constants: B=4, T=2048, E=2048, H=16, KV=4, G=4, D=128
// Fused QKV width: H*D + 2*KV*D = 3072
// ---------------------------------------------------------------------------

// Scratch (device-global: allocation-free per harness rules)
__device__ __half g_xh  [4 * 2048 * 2048];     // x half             32 MB
__device__ __half g_Wf  [3072 * 2048];         // [Wq;Wk;Wv]^T half  12 MB
__device__ __half g_Wot [2048 * 2048];         // Wo^T half           8 MB
__device__ __half g_QKV [4 * 2048 * 3072];     // fused QKV out      48 MB
__device__ __half g_Vt  [4 * 4 * 128 * 2048];  // (B,KV,D,T)          8 MB
__device__ __half g_AYh [4 * 2048 * 2048];     // attn out half      32 MB

DEV_INLINE uint32_t packh2(float lo, float hi) {
    __half2 h = __floats2half2_rn(lo, hi);
    return *reinterpret_cast<uint32_t*>(&h);
}
DEV_INLINE void mma16(float* c, const uint32_t* a, const uint32_t* b) {
    asm("mma.sync.aligned.m16n8k16.row.col.f32.f16.f16.f32 "
        "{%0,%1,%2,%3}, {%4,%5,%6,%7}, {%8,%9}, {%0,%1,%2,%3};"
        : "+f"(c[0]), "+f"(c[1]), "+f"(c[2]), "+f"(c[3])
        : "r"(a[0]), "r"(a[1]), "r"(a[2]), "r"(a[3]), "r"(b[0]), "r"(b[1]));
}
DEV_INLINE uint32_t sptr(const void* p) {
    return (uint32_t)__cvta_generic_to_shared(p);
}
DEV_INLINE void cp16(uint32_t dst, const void* src) {
    asm volatile("cp.async.cg.shared.global [%0], [%1], 16;" ::
                     "r"(dst), "l"(src));
}
DEV_INLINE void ldsm4(uint32_t* r, uint32_t addr) {
    asm volatile("ldmatrix.sync.aligned.m8n8.x4.shared.b16 {%0,%1,%2,%3}, [%4];"
                 : "=r"(r[0]), "=r"(r[1]), "=r"(r[2]), "=r"(r[3])
                 : "r"(addr));
}

// ---------------------------------------------------------------------------
// Prep kernels
// ---------------------------------------------------------------------------
__global__ __launch_bounds__(256) void f2h_kernel(const float* __restrict__ in,
                                                  __half* __restrict__ out) {
    int i = (blockIdx.x * 256 + threadIdx.x) * 4;
    float4 v = *(const float4*)(in + i);
    uint2 o;
    o.x = packh2(v.x, v.y);
    o.y = packh2(v.z, v.w);
    *(uint2*)(out + i) = o;
}

// Fused weight transpose: all four W (K=2048, N) f32 -> (N, 2048) half.
// grid (160, 64): bx<64 Wq | <80 Wk | <96 Wv | else Wo. Tile 32x32.
__global__ __launch_bounds__(256) void transpose_w4(
    const float* __restrict__ Wq, const float* __restrict__ Wk,
    const float* __restrict__ Wv, const float* __restrict__ Wo,
    __half* __restrict__ Wf, __half* __restrict__ Wot) {
    __shared__ float t[32][33];
    const int bx = blockIdx.x;
    const float* W;
    __half* Wt;
    int Ncols, n0;
    if (bx < 64) {
        W = Wq; Wt = Wf; Ncols = 2048; n0 = bx * 32;
    } else if (bx < 80) {
        W = Wk; Wt = Wf + (size_t)2048 * 2048; Ncols = 512; n0 = (bx - 64) * 32;
    } else if (bx < 96) {
        W = Wv; Wt = Wf + (size_t)2560 * 2048; Ncols = 512; n0 = (bx - 80) * 32;
    } else {
        W = Wo; Wt = Wot; Ncols = 2048; n0 = (bx - 96) * 32;
    }
    const int k0 = blockIdx.y * 32;
    const int lx = threadIdx.x & 31, ly = threadIdx.x >> 5;
#pragma unroll
    for (int i = 0; i < 4; i++)
        t[ly + 8 * i][lx] = W[(size_t)(k0 + ly + 8 * i) * Ncols + n0 + lx];
    __syncthreads();
#pragma unroll
    for (int i = 0; i < 4; i++)
        Wt[(size_t)(n0 + ly + 8 * i) * 2048 + k0 + lx] =
            __float2half(t[lx][ly + 8 * i]);
}

// ---------------------------------------------------------------------------
// fp16 GEMM: C(MxN) = A(M,K) @ Bt(N,K)^T.
// BM=128 BN=128 BK=32; 256 threads = 8 warps (2m x 4n); warp tile 64x32.
// 4-stage cp.async pipeline (3 tiles in flight), one barrier per iteration,
// ldmatrix fragments. smem rows 20 uint32 (80 B): conflict-free phases.
// (round-13 proven config)
// ---------------------------------------------------------------------------
template <int N, bool HALF_OUT>
__global__ __launch_bounds__(256) void gemm_hh(const __half* __restrict__ A,
                                               const __half* __restrict__ Bt,
                                               void* __restrict__ Cv) {
    constexpr int K = 2048;
    constexpr int NT = K / 32;
    constexpr int STG = 128 * 20;  // uint32 units per stage per operand
    extern __shared__ uint32_t smem[];

    const int tid = threadIdx.x;
    const int lane = tid & 31, wid = tid >> 5;
    const int g = lane >> 2, t = lane & 3;
    const int wm = wid & 1, wn = wid >> 1;
    const int bm = blockIdx.y * 128, bn = blockIdx.x * 128;

    const int l_row = tid >> 1;       // 0..127
    const int l_u0  = (tid & 1) * 8;  // unit 0 or 8

    const __half* gA = A + (size_t)(bm + l_row) * K + 2 * l_u0;
    const __half* gB = Bt + (size_t)(bn + l_row) * K + 2 * l_u0;

    const uint32_t sA = sptr(smem);
    const uint32_t sB = sA + 4 * STG * 4;
    const uint32_t stA = sA + l_row * 80 + l_u0 * 4;
    const uint32_t stB = sB + l_row * 80 + l_u0 * 4;

    const uint32_t aAddr =
        sA + (wm * 64 + (lane & 7) + ((lane >> 3) & 1) * 8) * 80 +
        ((lane >> 4) * 4) * 4;
    const uint32_t bAddr =
        sB + (wn * 32 + (lane & 7) + ((lane >> 4) & 1) * 8) * 80 +
        (((lane >> 3) & 1) * 4) * 4;

    float acc[4][4][4];
#pragma unroll
    for (int mi = 0; mi < 4; mi++)
#pragma unroll
        for (int ni = 0; ni < 4; ni++)
#pragma unroll
            for (int j = 0; j < 4; j++) acc[mi][ni][j] = 0.f;

    auto issue = [&](int kt) {
        const uint32_t off = (kt & 3) * STG * 4;
        const __half* a = gA + kt * 32;
        cp16(stA + off, a);
        cp16(stA + off + 16, a + 8);
        const __half* b = gB + kt * 32;
        cp16(stB + off, b);
        cp16(stB + off + 16, b + 8);
        asm volatile("cp.async.commit_group;" ::: "memory");
    };

    issue(0);
    issue(1);
    issue(2);

    for (int kt = 0; kt < NT; kt++) {
        if (kt < NT - 2)
            asm volatile("cp.async.wait_group 2;" ::: "memory");
        else if (kt == NT - 2)
            asm volatile("cp.async.wait_group 1;" ::: "memory");
        else
            asm volatile("cp.async.wait_group 0;" ::: "memory");
        __syncthreads();
        if (kt + 3 < NT) issue(kt + 3);

        const uint32_t soff = (kt & 3) * STG * 4;
#pragma unroll
        for (int ks = 0; ks < 2; ks++) {
            uint32_t aF[4][4], bF[2][4];
#pragma unroll
            for (int mi = 0; mi < 4; mi++)
                ldsm4(aF[mi], aAddr + soff + mi * 16 * 80 + ks * 32);
            ldsm4(bF[0], bAddr + soff + ks * 32);
            ldsm4(bF[1], bAddr + soff + 16 * 80 + ks * 32);
#pragma unroll
            for (int ni = 0; ni < 4; ni++) {
                const uint32_t* bp = &bF[ni >> 1][(ni & 1) * 2];
#pragma unroll
                for (int mi = 0; mi < 4; mi++) mma16(acc[mi][ni], aF[mi], bp);
            }
        }
    }

    // epilogue
#pragma unroll
    for (int mi = 0; mi < 4; mi++) {
        int r0 = bm + wm * 64 + mi * 16 + g;
#pragma unroll
        for (int ni = 0; ni < 4; ni++) {
            int cN = bn + wn * 32 + ni * 8 + 2 * t;
            if (HALF_OUT) {
                __half* C = (__half*)Cv;
                *reinterpret_cast<__half2*>(C + (size_t)r0 * N + cN) =
                    __floats2half2_rn(acc[mi][ni][0], acc[mi][ni][1]);
                *reinterpret_cast<__half2*>(C + (size_t)(r0 + 8) * N + cN) =
                    __floats2half2_rn(acc[mi][ni][2], acc[mi][ni][3]);
            } else {
                float* C = (float*)Cv;
                *(float2*)(C + (size_t)r0 * N + cN) =
                    make_float2(acc[mi][ni][0], acc[mi][ni][1]);
                *(float2*)(C + (size_t)(r0 + 8) * N + cN) =
                    make_float2(acc[mi][ni][2], acc[mi][ni][3]);
            }
        }
    }
}

// ---------------------------------------------------------------------------
// V transpose: V slice of fused QKV (row stride 3072) -> g_Vt (B,KV,D,T),
// key-pair packed half2.
// ---------------------------------------------------------------------------
__global__ __launch_bounds__(256) void transpose_v(const __half* __restrict__ C,
                                                   __half* __restrict__ Vt) {
    __shared__ uint32_t U[64][33];
    const int tid = threadIdx.x;
    const int k0 = blockIdx.x * 64;
    const int kv = blockIdx.y >> 1;
    const int d0 = (blockIdx.y & 1) * 64;
    const int b  = blockIdx.z;

    const uint32_t* in = reinterpret_cast<const uint32_t*>(C);
    {
        int dp = tid & 31;
        int krow = tid >> 5;
#pragma unroll
        for (int i = 0; i < 8; i++) {
            int key = i * 8 + krow;
            U[key][dp] = in[(size_t)(b * 2048 + k0 + key) * 1536 + 1280 +
                            kv * 64 + (d0 >> 1) + dp];
        }
    }
    __syncthreads();
    uint32_t* out = reinterpret_cast<uint32_t*>(Vt);
    {
        int kp = tid & 31;
        int drow = tid >> 5;
#pragma unroll
        for (int i = 0; i < 8; i++) {
            int d = i * 8 + drow;
            uint32_t a = U[2 * kp][d >> 1];
            uint32_t c = U[2 * kp + 1][d >> 1];
            uint32_t lo = (d & 1) ? (a >> 16) : (a & 0xffffu);
            uint32_t hi = (d & 1) ? (c >> 16) : (c & 0xffffu);
            out[(size_t)((b * 4 + kv) * 128 + d0 + d) * 1024 + (k0 >> 1) + kp] =
                lo | (hi << 16);
        }
    }
}

// ---------------------------------------------------------------------------
// Flash attention (causal, GQA), fp16 m16n8k16 core, f32 softmax/accum.
// Grid (T/64, H, B), 128 threads = 4 warps; warp owns 16 query rows.
// Double-buffered cp.async K/V tiles. Dynamic smem 60416 B.
// NEW (only change this round): longest-first CTA ordering —
//   qb = gridDim.x-1-blockIdx.x, so big-causal-range CTAs launch first (LPT).
// Numerics identical per query row.
// ---------------------------------------------------------------------------
static constexpr int QS_U = 0;
static constexpr int KS_U = 4352;
static constexpr int KS_STG = 2176;  // 32*68
static constexpr int VS_U = 8704;
static constexpr int VS_STG = 2560;  // 128*20
static constexpr int PS_U = 13824;
static constexpr int ATTN_SMEM = 15104 * 4;  // 60416 B

__global__ __launch_bounds__(128) void attn_f16(const __half* __restrict__ Cqkv,
                                                const __half* __restrict__ Vt,
                                                __half* __restrict__ Y) {
    extern __shared__ uint32_t dsm[];

    const int b = blockIdx.z, h = blockIdx.y;
    const int qb = gridDim.x - 1 - blockIdx.x;  // longest-first scheduling
    const int kv = h >> 2;
    const int tid = threadIdx.x, w = tid >> 5, lane = tid & 31;
    const int g = lane >> 2, t = lane & 3;
    const float scale = 0.08838834764831845f;

    const uint4* Cv = reinterpret_cast<const uint4*>(Cqkv);
    const uint32_t smb = sptr(dsm);

    const uint32_t qAddr =
        smb + QS_U * 4 +
        (w * 16 + (lane & 7) + ((lane >> 3) & 1) * 8) * 272 +
        ((lane >> 4) * 4) * 4;
    const uint32_t kAddr0 =
        smb + KS_U * 4 + ((lane & 7) + ((lane >> 4) & 1) * 8) * 272 +
        (((lane >> 3) & 1) * 4) * 4;
    const uint32_t vAddr0 =
        smb + VS_U * 4 + ((lane & 7) + ((lane >> 4) & 1) * 8) * 80 +
        (((lane >> 3) & 1) * 4) * 4;
    const uint32_t pAddr =
        smb + (PS_U + w * 320) * 4 + ((lane & 7) + ((lane >> 3) & 1) * 8) * 80 +
        ((lane >> 4) * 4) * 4;

    const int kr = tid >> 2, kc = tid & 3;
    const uint32_t kDst = smb + KS_U * 4 + kr * 272 + kc * 64;
    const __half* kSrc0 =
        Cqkv + (size_t)(b * 2048 + kr) * 3072 + 2048 + kv * 128 + kc * 32;
    const uint32_t vDst = smb + VS_U * 4 + tid * 80;
    const __half* vSrc0 = Vt + (size_t)((b * 4 + kv) * 128 + tid) * 2048;

    // Stage Q block: 64 rows x 16 uint4 (row stride 3072 half = 384 uint4)
    {
        int r = tid >> 1, q = tid & 1;
        size_t base = (size_t)(b * 2048 + qb * 64 + r) * 384 + h * 16;
#pragma unroll
        for (int j = 0; j < 8; j++) {
            uint4 v = Cv[base + q * 8 + j];
            *(uint4*)&dsm[QS_U + r * 68 + (q * 8 + j) * 4] = v;
        }
    }

    const int ntiles = qb * 2 + 2;

    auto issue = [&](int jt) {
        const uint32_t kOff = (jt & 1) * KS_STG * 4;
        const uint32_t vOff = (jt & 1) * VS_STG * 4;
        const __half* ks = kSrc0 + (size_t)(jt * 32) * 3072;
#pragma unroll
        for (int j = 0; j < 4; j++) cp16(kDst + kOff + j * 16, ks + j * 8);
        const __half* vs = vSrc0 + jt * 32;
#pragma unroll
        for (int j = 0; j < 4; j++) cp16(vDst + vOff + j * 16, vs + j * 8);
        asm volatile("cp.async.commit_group;" ::: "memory");
    };

    issue(0);
    __syncthreads();

    uint32_t qF[8][4];
#pragma unroll
    for (int ks = 0; ks < 8; ks++) ldsm4(qF[ks], qAddr + ks * 32);

    float O[16][4];
#pragma unroll
    for (int i = 0; i < 16; i++)
#pragma unroll
        for (int j = 0; j < 4; j++) O[i][j] = 0.f;
    float m0 = -1e30f, m1 = -1e30f, l0 = 0.f, l1 = 0.f;

    const int qr0 = qb * 64 + w * 16 + g;
    const int qr1 = qr0 + 8;
    const int qmaxw = qb * 64 + w * 16 + 15;

    for (int jt = 0; jt < ntiles; jt++) {
        const int jbase = jt * 32;
        if (jt + 1 < ntiles) issue(jt + 1);
        if (jt + 1 < ntiles)
            asm volatile("cp.async.wait_group 1;" ::: "memory");
        else
            asm volatile("cp.async.wait_group 0;" ::: "memory");
        __syncthreads();

        if (jbase <= qmaxw) {
            const uint32_t kAddr = kAddr0 + (jt & 1) * KS_STG * 4;
            const uint32_t vAddr = vAddr0 + (jt & 1) * VS_STG * 4;

            float s[4][4];
#pragma unroll
            for (int ni = 0; ni < 4; ni++)
#pragma unroll
                for (int j = 0; j < 4; j++) s[ni][j] = 0.f;
#pragma unroll
            for (int ks = 0; ks < 8; ks++) {
                uint32_t kA[4], kB[4];
                ldsm4(kA, kAddr + ks * 32);
                ldsm4(kB, kAddr + 16 * 272 + ks * 32);
                mma16(s[0], qF[ks], kA);
                mma16(s[1], qF[ks], kA + 2);
                mma16(s[2], qF[ks], kB);
                mma16(s[3], qF[ks], kB + 2);
            }

#pragma unroll
            for (int ni = 0; ni < 4; ni++) {
                int col = jbase + ni * 8 + 2 * t;
                s[ni][0] = (col     <= qr0) ? s[ni][0] * scale : -1e30f;
                s[ni][1] = (col + 1 <= qr0) ? s[ni][1] * scale : -1e30f;
                s[ni][2] = (col     <= qr1) ? s[ni][2] * scale : -1e30f;
                s[ni][3] = (col + 1 <= qr1) ? s[ni][3] * scale : -1e30f;
            }

            float tm0 = -1e30f, tm1 = -1e30f;
#pragma unroll
            for (int ni = 0; ni < 4; ni++) {
                tm0 = fmaxf(tm0, fmaxf(s[ni][0], s[ni][1]));
                tm1 = fmaxf(tm1, fmaxf(s[ni][2], s[ni][3]));
            }
            tm0 = fmaxf(tm0, __shfl_xor_sync(0xffffffffu, tm0, 1));
            tm0 = fmaxf(tm0, __shfl_xor_sync(0xffffffffu, tm0, 2));
            tm1 = fmaxf(tm1, __shfl_xor_sync(0xffffffffu, tm1, 1));
            tm1 = fmaxf(tm1, __shfl_xor_sync(0xffffffffu, tm1, 2));
            float nm0 = fmaxf(m0, tm0), nm1 = fmaxf(m1, tm1);
            float corr0 = __expf(m0 - nm0), corr1 = __expf(m1 - nm1);

            float ls0 = 0.f, ls1 = 0.f;
#pragma unroll
            for (int ni = 0; ni < 4; ni++) {
                s[ni][0] = __expf(s[ni][0] - nm0);
                s[ni][1] = __expf(s[ni][1] - nm0);
                s[ni][2] = __expf(s[ni][2] - nm1);
                s[ni][3] = __expf(s[ni][3] - nm1);
                ls0 += s[ni][0] + s[ni][1];
                ls1 += s[ni][2] + s[ni][3];
            }
            ls0 += __shfl_xor_sync(0xffffffffu, ls0, 1);
            ls0 += __shfl_xor_sync(0xffffffffu, ls0, 2);
            ls1 += __shfl_xor_sync(0xffffffffu, ls1, 1);
            ls1 += __shfl_xor_sync(0xffffffffu, ls1, 2);
            l0 = l0 * corr0 + ls0;
            l1 = l1 * corr1 + ls1;
            m0 = nm0;
            m1 = nm1;

#pragma unroll
            for (int nf = 0; nf < 16; nf++) {
                O[nf][0] *= corr0; O[nf][1] *= corr0;
                O[nf][2] *= corr1; O[nf][3] *= corr1;
            }

#pragma unroll
            for (int ni = 0; ni < 4; ni++) {
                dsm[PS_U + w * 320 + g * 20 + ni * 4 + t] =
                    packh2(s[ni][0], s[ni][1]);
                dsm[PS_U + w * 320 + (g + 8) * 20 + ni * 4 + t] =
                    packh2(s[ni][2], s[ni][3]);
            }
            __syncwarp();

#pragma unroll
            for (int ks2 = 0; ks2 < 2; ks2++) {
                uint32_t aP[4];
                ldsm4(aP, pAddr + ks2 * 32);
#pragma unroll
                for (int nj = 0; nj < 8; nj++) {
                    uint32_t vF[4];
                    ldsm4(vF, vAddr + nj * 16 * 80 + ks2 * 32);
                    mma16(O[nj * 2], aP, vF);
                    mma16(O[nj * 2 + 1], aP, vF + 2);
                }
            }
        }
        __syncthreads();
    }

    __half* Yb = Y + ((size_t)(b * 2048 + qb * 64)) * 2048 + h * 128;
    float inv0 = 1.f / l0, inv1 = 1.f / l1;
#pragma unroll
    for (int nf = 0; nf < 16; nf++) {
        int cN = nf * 8 + 2 * t;
        *reinterpret_cast<__half2*>(Yb + (size_t)(w * 16 + g) * 2048 + cN) =
            __floats2half2_rn(O[nf][0] * inv0, O[nf][1] * inv0);
        *reinterpret_cast<__half2*>(Yb + (size_t)(w * 16 + g + 8) * 2048 + cN) =
            __floats2half2_rn(O[nf][2] * inv1, O[nf][3] * inv1);
    }
}

// ---------------------------------------------------------------------------
// Launch
// ---------------------------------------------------------------------------
extern "C" void kernel_launch(void* const* d_in, const int* in_sizes, int n_in,
                              void* d_out, int out_size) {
    (void)in_sizes; (void)n_in; (void)out_size;
    const float* x  = (const float*)d_in[0];
    const float* Wq = (const float*)d_in[1];
    const float* Wk = (const float*)d_in[2];
    const float* Wv = (const float*)d_in[3];
    const float* Wo = (const float*)d_in[4];
    float* out = (float*)d_out;

    __half *xh, *Wf, *Wot, *Cqkv, *Vtp, *AYp;
    cudaGetSymbolAddress((void**)&xh,   g_xh);
    cudaGetSymbolAddress((void**)&Wf,   g_Wf);
    cudaGetSymbolAddress((void**)&Wot,  g_Wot);
    cudaGetSymbolAddress((void**)&Cqkv, g_QKV);
    cudaGetSymbolAddress((void**)&Vtp,  g_Vt);
    cudaGetSymbolAddress((void**)&AYp,  g_AYh);

    const int SMEM_GEMM = 8 * 128 * 20 * 4;  // 81920 B (4 stages x A,B)
    cudaFuncSetAttribute(gemm_hh<3072, true>,
                         cudaFuncAttributeMaxDynamicSharedMemorySize, SMEM_GEMM);
    cudaFuncSetAttribute(gemm_hh<2048, false>,
                         cudaFuncAttributeMaxDynamicSharedMemorySize, SMEM_GEMM);
    cudaFuncSetAttribute(attn_f16,
                         cudaFuncAttributeMaxDynamicSharedMemorySize, ATTN_SMEM);

    // Stage 0: prep (x -> half; all 4 weights -> transposed half, one launch)
    f2h_kernel<<<4 * 2048 * 2048 / 1024, 256>>>(x, xh);
    transpose_w4<<<dim3(160, 64), 256>>>(Wq, Wk, Wv, Wo, Wf, Wot);

    // Stage 1: fused QKV projection (M=8192, N=3072, K=2048)
    gemm_hh<3072, true><<<dim3(24, 64), 256, SMEM_GEMM>>>(xh, Wf, Cqkv);

    // Stage 1b: transpose V slice into (B,KV,D,T) key-pair-packed layout
    transpose_v<<<dim3(32, 8, 4), 256>>>(Cqkv, Vtp);

    // Stage 2: causal GQA flash attention (longest-first CTA order)
    attn_f16<<<dim3(32, 16, 4), 128, ATTN_SMEM>>>(Cqkv, Vtp, AYp);

    // Stage 3: output projection (M=8192, N=2048), f32 out
    gemm_hh<2048, false><<<dim3(16, 64), 256, SMEM_GEMM>>>(AYp, Wot, out);
}

// round 16
// speedup vs baseline: 1.0739x; 1.0321x over previous
#include <cuda_runtime.h>
#include <cuda_fp16.h>
#include <cstdint>

#define DEV_INLINE __device__ __forceinline__

// ---------------------------------------------------------------------------
// Problem constants: B=4, T=2048, E=2048, H=16, KV=4, G=4, D=128
// Fused QKV width: H*D + 2*KV*D = 3072
// ---------------------------------------------------------------------------

// Scratch (device-global: allocation-free per harness rules)
__device__ __half g_xh  [4 * 2048 * 2048];     // x half             32 MB
__device__ __half g_Wf  [3072 * 2048];         // [Wq;Wk;Wv]^T half  12 MB
__device__ __half g_Wot [2048 * 2048];         // Wo^T half           8 MB
__device__ __half g_QKV [4 * 2048 * 3072];     // fused QKV out      48 MB
__device__ __half g_AYh [4 * 2048 * 2048];     // attn out half      32 MB

DEV_INLINE uint32_t packh2(float lo, float hi) {
    __half2 h = __floats2half2_rn(lo, hi);
    return *reinterpret_cast<uint32_t*>(&h);
}
DEV_INLINE void mma16(float* c, const uint32_t* a, const uint32_t* b) {
    asm("mma.sync.aligned.m16n8k16.row.col.f32.f16.f16.f32 "
        "{%0,%1,%2,%3}, {%4,%5,%6,%7}, {%8,%9}, {%0,%1,%2,%3};"
        : "+f"(c[0]), "+f"(c[1]), "+f"(c[2]), "+f"(c[3])
        : "r"(a[0]), "r"(a[1]), "r"(a[2]), "r"(a[3]), "r"(b[0]), "r"(b[1]));
}
DEV_INLINE uint32_t sptr(const void* p) {
    return (uint32_t)__cvta_generic_to_shared(p);
}
DEV_INLINE void cp16(uint32_t dst, const void* src) {
    asm volatile("cp.async.cg.shared.global [%0], [%1], 16;" ::
                     "r"(dst), "l"(src));
}
DEV_INLINE void ldsm4(uint32_t* r, uint32_t addr) {
    asm volatile("ldmatrix.sync.aligned.m8n8.x4.shared.b16 {%0,%1,%2,%3}, [%4];"
                 : "=r"(r[0]), "=r"(r[1]), "=r"(r[2]), "=r"(r[3])
                 : "r"(addr));
}
DEV_INLINE void ldsm4t(uint32_t* r, uint32_t addr) {
    asm volatile(
        "ldmatrix.sync.aligned.m8n8.x4.trans.shared.b16 {%0,%1,%2,%3}, [%4];"
        : "=r"(r[0]), "=r"(r[1]), "=r"(r[2]), "=r"(r[3])
        : "r"(addr));
}

// ---------------------------------------------------------------------------
// Prep kernels
// ---------------------------------------------------------------------------
__global__ __launch_bounds__(256) void f2h_kernel(const float* __restrict__ in,
                                                  __half* __restrict__ out) {
    int i = (blockIdx.x * 256 + threadIdx.x) * 4;
    float4 v = *(const float4*)(in + i);
    uint2 o;
    o.x = packh2(v.x, v.y);
    o.y = packh2(v.z, v.w);
    *(uint2*)(out + i) = o;
}

// Fused weight transpose: all four W (K=2048, N) f32 -> (N, 2048) half.
// grid (160, 64): bx<64 Wq | <80 Wk | <96 Wv | else Wo. Tile 32x32.
__global__ __launch_bounds__(256) void transpose_w4(
    const float* __restrict__ Wq, const float* __restrict__ Wk,
    const float* __restrict__ Wv, const float* __restrict__ Wo,
    __half* __restrict__ Wf, __half* __restrict__ Wot) {
    __shared__ float t[32][33];
    const int bx = blockIdx.x;
    const float* W;
    __half* Wt;
    int Ncols, n0;
    if (bx < 64) {
        W = Wq; Wt = Wf; Ncols = 2048; n0 = bx * 32;
    } else if (bx < 80) {
        W = Wk; Wt = Wf + (size_t)2048 * 2048; Ncols = 512; n0 = (bx - 64) * 32;
    } else if (bx < 96) {
        W = Wv; Wt = Wf + (size_t)2560 * 2048; Ncols = 512; n0 = (bx - 80) * 32;
    } else {
        W = Wo; Wt = Wot; Ncols = 2048; n0 = (bx - 96) * 32;
    }
    const int k0 = blockIdx.y * 32;
    const int lx = threadIdx.x & 31, ly = threadIdx.x >> 5;
#pragma unroll
    for (int i = 0; i < 4; i++)
        t[ly + 8 * i][lx] = W[(size_t)(k0 + ly + 8 * i) * Ncols + n0 + lx];
    __syncthreads();
#pragma unroll
    for (int i = 0; i < 4; i++)
        Wt[(size_t)(n0 + ly + 8 * i) * 2048 + k0 + lx] =
            __float2half(t[lx][ly + 8 * i]);
}

// ---------------------------------------------------------------------------
// fp16 GEMM: C(MxN) = A(M,K) @ Bt(N,K)^T.
// BM=128 BN=128 BK=32; 256 threads = 8 warps (2m x 4n); warp tile 64x32.
// 4-stage cp.async pipeline (3 tiles in flight), one barrier per iteration,
// ldmatrix fragments. smem rows 20 uint32 (80 B): conflict-free phases.
// (round-13 proven config)
// ---------------------------------------------------------------------------
template <int N, bool HALF_OUT>
__global__ __launch_bounds__(256) void gemm_hh(const __half* __restrict__ A,
                                               const __half* __restrict__ Bt,
                                               void* __restrict__ Cv) {
    constexpr int K = 2048;
    constexpr int NT = K / 32;
    constexpr int STG = 128 * 20;  // uint32 units per stage per operand
    extern __shared__ uint32_t smem[];

    const int tid = threadIdx.x;
    const int lane = tid & 31, wid = tid >> 5;
    const int g = lane >> 2, t = lane & 3;
    const int wm = wid & 1, wn = wid >> 1;
    const int bm = blockIdx.y * 128, bn = blockIdx.x * 128;

    const int l_row = tid >> 1;       // 0..127
    const int l_u0  = (tid & 1) * 8;  // unit 0 or 8

    const __half* gA = A + (size_t)(bm + l_row) * K + 2 * l_u0;
    const __half* gB = Bt + (size_t)(bn + l_row) * K + 2 * l_u0;

    const uint32_t sA = sptr(smem);
    const uint32_t sB = sA + 4 * STG * 4;
    const uint32_t stA = sA + l_row * 80 + l_u0 * 4;
    const uint32_t stB = sB + l_row * 80 + l_u0 * 4;

    const uint32_t aAddr =
        sA + (wm * 64 + (lane & 7) + ((lane >> 3) & 1) * 8) * 80 +
        ((lane >> 4) * 4) * 4;
    const uint32_t bAddr =
        sB + (wn * 32 + (lane & 7) + ((lane >> 4) & 1) * 8) * 80 +
        (((lane >> 3) & 1) * 4) * 4;

    float acc[4][4][4];
#pragma unroll
    for (int mi = 0; mi < 4; mi++)
#pragma unroll
        for (int ni = 0; ni < 4; ni++)
#pragma unroll
            for (int j = 0; j < 4; j++) acc[mi][ni][j] = 0.f;

    auto issue = [&](int kt) {
        const uint32_t off = (kt & 3) * STG * 4;
        const __half* a = gA + kt * 32;
        cp16(stA + off, a);
        cp16(stA + off + 16, a + 8);
        const __half* b = gB + kt * 32;
        cp16(stB + off, b);
        cp16(stB + off + 16, b + 8);
        asm volatile("cp.async.commit_group;" ::: "memory");
    };

    issue(0);
    issue(1);
    issue(2);

    for (int kt = 0; kt < NT; kt++) {
        if (kt < NT - 2)
            asm volatile("cp.async.wait_group 2;" ::: "memory");
        else if (kt == NT - 2)
            asm volatile("cp.async.wait_group 1;" ::: "memory");
        else
            asm volatile("cp.async.wait_group 0;" ::: "memory");
        __syncthreads();
        if (kt + 3 < NT) issue(kt + 3);

        const uint32_t soff = (kt & 3) * STG * 4;
#pragma unroll
        for (int ks = 0; ks < 2; ks++) {
            uint32_t aF[4][4], bF[2][4];
#pragma unroll
            for (int mi = 0; mi < 4; mi++)
                ldsm4(aF[mi], aAddr + soff + mi * 16 * 80 + ks * 32);
            ldsm4(bF[0], bAddr + soff + ks * 32);
            ldsm4(bF[1], bAddr + soff + 16 * 80 + ks * 32);
#pragma unroll
            for (int ni = 0; ni < 4; ni++) {
                const uint32_t* bp = &bF[ni >> 1][(ni & 1) * 2];
#pragma unroll
                for (int mi = 0; mi < 4; mi++) mma16(acc[mi][ni], aF[mi], bp);
            }
        }
    }

    // epilogue
#pragma unroll
    for (int mi = 0; mi < 4; mi++) {
        int r0 = bm + wm * 64 + mi * 16 + g;
#pragma unroll
        for (int ni = 0; ni < 4; ni++) {
            int cN = bn + wn * 32 + ni * 8 + 2 * t;
            if (HALF_OUT) {
                __half* C = (__half*)Cv;
                *reinterpret_cast<__half2*>(C + (size_t)r0 * N + cN) =
                    __floats2half2_rn(acc[mi][ni][0], acc[mi][ni][1]);
                *reinterpret_cast<__half2*>(C + (size_t)(r0 + 8) * N + cN) =
                    __floats2half2_rn(acc[mi][ni][2], acc[mi][ni][3]);
            } else {
                float* C = (float*)Cv;
                *(float2*)(C + (size_t)r0 * N + cN) =
                    make_float2(acc[mi][ni][0], acc[mi][ni][1]);
                *(float2*)(C + (size_t)(r0 + 8) * N + cN) =
                    make_float2(acc[mi][ni][2], acc[mi][ni][3]);
            }
        }
    }
}

// ---------------------------------------------------------------------------
// Flash attention (causal, GQA), fp16 m16n8k16 core, f32 softmax/accum.
// Grid (T/64, H, B), 128 threads = 4 warps; warp owns 16 query rows.
// Double-buffered cp.async K/V tiles; longest-first CTA order (LPT).
// NEW (only change this round): V is loaded K-major straight from the fused
// QKV tensor (no transpose_v kernel, no g_Vt) and fragments for P@V come
// from ldmatrix.x4.trans — {r0,r1}=n-block0, {r2,r3}=n-block1.
// Smem layout (uint32 units): Qs[0,4352) Ks[4352,+4352) Vk[8704,+4352)
// Ps[13056,+1280) -> 14336 units = 57344 B.
// ---------------------------------------------------------------------------
static constexpr int QS_U = 0;
static constexpr int KS_U = 4352;
static constexpr int KS_STG = 2176;  // 32*68
static constexpr int VK_U = 8704;
static constexpr int VK_STG = 2176;  // 32*68
static constexpr int PS_U = 13056;
static constexpr int ATTN_SMEM = 14336 * 4;  // 57344 B

__global__ __launch_bounds__(128) void attn_f16(const __half* __restrict__ Cqkv,
                                                __half* __restrict__ Y) {
    extern __shared__ uint32_t dsm[];

    const int b = blockIdx.z, h = blockIdx.y;
    const int qb = gridDim.x - 1 - blockIdx.x;  // longest-first scheduling
    const int kv = h >> 2;
    const int tid = threadIdx.x, w = tid >> 5, lane = tid & 31;
    const int g = lane >> 2, t = lane & 3;
    const float scale = 0.08838834764831845f;

    const uint4* Cv = reinterpret_cast<const uint4*>(Cqkv);
    const uint32_t smb = sptr(dsm);

    const uint32_t qAddr =
        smb + QS_U * 4 +
        (w * 16 + (lane & 7) + ((lane >> 3) & 1) * 8) * 272 +
        ((lane >> 4) * 4) * 4;
    const uint32_t kAddr0 =
        smb + KS_U * 4 + ((lane & 7) + ((lane >> 4) & 1) * 8) * 272 +
        (((lane >> 3) & 1) * 4) * 4;
    // trans V fragment base: row = key = (lane&7) + 8*((lane>>3)&1),
    // col halfs = 8*(lane>>4); per ks2 add 16 rows, per d16-block add 32 B.
    const uint32_t vAddrT0 =
        smb + VK_U * 4 + ((lane & 7) + ((lane >> 3) & 1) * 8) * 272 +
        (lane >> 4) * 16;
    const uint32_t pAddr =
        smb + (PS_U + w * 320) * 4 + ((lane & 7) + ((lane >> 3) & 1) * 8) * 80 +
        ((lane >> 4) * 4) * 4;

    // cp.async loader mapping: 32 rows x 4 col-groups(64B) for K and V
    const int kr = tid >> 2, kc = tid & 3;
    const uint32_t kDst = smb + KS_U * 4 + kr * 272 + kc * 64;
    const uint32_t vDst = smb + VK_U * 4 + kr * 272 + kc * 64;
    const __half* kSrc0 =
        Cqkv + (size_t)(b * 2048 + kr) * 3072 + 2048 + kv * 128 + kc * 32;
    const __half* vSrc0 = kSrc0 + 512;  // V slice sits 512 halfs after K

    // Stage Q block: 64 rows x 16 uint4 (row stride 3072 half = 384 uint4)
    {
        int r = tid >> 1, q = tid & 1;
        size_t base = (size_t)(b * 2048 + qb * 64 + r) * 384 + h * 16;
#pragma unroll
        for (int j = 0; j < 8; j++) {
            uint4 v = Cv[base + q * 8 + j];
            *(uint4*)&dsm[QS_U + r * 68 + (q * 8 + j) * 4] = v;
        }
    }

    const int ntiles = qb * 2 + 2;

    auto issue = [&](int jt) {
        const uint32_t kOff = (jt & 1) * KS_STG * 4;
        const uint32_t vOff = (jt & 1) * VK_STG * 4;
        const __half* ks = kSrc0 + (size_t)(jt * 32) * 3072;
        const __half* vs = vSrc0 + (size_t)(jt * 32) * 3072;
#pragma unroll
        for (int j = 0; j < 4; j++) cp16(kDst + kOff + j * 16, ks + j * 8);
#pragma unroll
        for (int j = 0; j < 4; j++) cp16(vDst + vOff + j * 16, vs + j * 8);
        asm volatile("cp.async.commit_group;" ::: "memory");
    };

    issue(0);
    __syncthreads();

    uint32_t qF[8][4];
#pragma unroll
    for (int ks = 0; ks < 8; ks++) ldsm4(qF[ks], qAddr + ks * 32);

    float O[16][4];
#pragma unroll
    for (int i = 0; i < 16; i++)
#pragma unroll
        for (int j = 0; j < 4; j++) O[i][j] = 0.f;
    float m0 = -1e30f, m1 = -1e30f, l0 = 0.f, l1 = 0.f;

    const int qr0 = qb * 64 + w * 16 + g;
    const int qr1 = qr0 + 8;
    const int qmaxw = qb * 64 + w * 16 + 15;

    for (int jt = 0; jt < ntiles; jt++) {
        const int jbase = jt * 32;
        if (jt + 1 < ntiles) issue(jt + 1);
        if (jt + 1 < ntiles)
            asm volatile("cp.async.wait_group 1;" ::: "memory");
        else
            asm volatile("cp.async.wait_group 0;" ::: "memory");
        __syncthreads();

        if (jbase <= qmaxw) {
            const uint32_t kAddr = kAddr0 + (jt & 1) * KS_STG * 4;
            const uint32_t vAddrT = vAddrT0 + (jt & 1) * VK_STG * 4;

            float s[4][4];
#pragma unroll
            for (int ni = 0; ni < 4; ni++)
#pragma unroll
                for (int j = 0; j < 4; j++) s[ni][j] = 0.f;
#pragma unroll
            for (int ks = 0; ks < 8; ks++) {
                uint32_t kA[4], kB[4];
                ldsm4(kA, kAddr + ks * 32);
                ldsm4(kB, kAddr + 16 * 272 + ks * 32);
                mma16(s[0], qF[ks], kA);
                mma16(s[1], qF[ks], kA + 2);
                mma16(s[2], qF[ks], kB);
                mma16(s[3], qF[ks], kB + 2);
            }

#pragma unroll
            for (int ni = 0; ni < 4; ni++) {
                int col = jbase + ni * 8 + 2 * t;
                s[ni][0] = (col     <= qr0) ? s[ni][0] * scale : -1e30f;
                s[ni][1] = (col + 1 <= qr0) ? s[ni][1] * scale : -1e30f;
                s[ni][2] = (col     <= qr1) ? s[ni][2] * scale : -1e30f;
                s[ni][3] = (col + 1 <= qr1) ? s[ni][3] * scale : -1e30f;
            }

            float tm0 = -1e30f, tm1 = -1e30f;
#pragma unroll
            for (int ni = 0; ni < 4; ni++) {
                tm0 = fmaxf(tm0, fmaxf(s[ni][0], s[ni][1]));
                tm1 = fmaxf(tm1, fmaxf(s[ni][2], s[ni][3]));
            }
            tm0 = fmaxf(tm0, __shfl_xor_sync(0xffffffffu, tm0, 1));
            tm0 = fmaxf(tm0, __shfl_xor_sync(0xffffffffu, tm0, 2));
            tm1 = fmaxf(tm1, __shfl_xor_sync(0xffffffffu, tm1, 1));
            tm1 = fmaxf(tm1, __shfl_xor_sync(0xffffffffu, tm1, 2));
            float nm0 = fmaxf(m0, tm0), nm1 = fmaxf(m1, tm1);
            float corr0 = __expf(m0 - nm0), corr1 = __expf(m1 - nm1);

            float ls0 = 0.f, ls1 = 0.f;
#pragma unroll
            for (int ni = 0; ni < 4; ni++) {
                s[ni][0] = __expf(s[ni][0] - nm0);
                s[ni][1] = __expf(s[ni][1] - nm0);
                s[ni][2] = __expf(s[ni][2] - nm1);
                s[ni][3] = __expf(s[ni][3] - nm1);
                ls0 += s[ni][0] + s[ni][1];
                ls1 += s[ni][2] + s[ni][3];
            }
            ls0 += __shfl_xor_sync(0xffffffffu, ls0, 1);
            ls0 += __shfl_xor_sync(0xffffffffu, ls0, 2);
            ls1 += __shfl_xor_sync(0xffffffffu, ls1, 1);
            ls1 += __shfl_xor_sync(0xffffffffu, ls1, 2);
            l0 = l0 * corr0 + ls0;
            l1 = l1 * corr1 + ls1;
            m0 = nm0;
            m1 = nm1;

#pragma unroll
            for (int nf = 0; nf < 16; nf++) {
                O[nf][0] *= corr0; O[nf][1] *= corr0;
                O[nf][2] *= corr1; O[nf][3] *= corr1;
            }

#pragma unroll
            for (int ni = 0; ni < 4; ni++) {
                dsm[PS_U + w * 320 + g * 20 + ni * 4 + t] =
                    packh2(s[ni][0], s[ni][1]);
                dsm[PS_U + w * 320 + (g + 8) * 20 + ni * 4 + t] =
                    packh2(s[ni][2], s[ni][3]);
            }
            __syncwarp();

            // O += P @ V   (16x32 @ 32x128), 2 k16-steps; V frags via
            // ldmatrix.trans on the K-major V tile.
#pragma unroll
            for (int ks2 = 0; ks2 < 2; ks2++) {
                uint32_t aP[4];
                ldsm4(aP, pAddr + ks2 * 32);
                const uint32_t vBase = vAddrT + ks2 * 16 * 272;
#pragma unroll
                for (int dj = 0; dj < 8; dj++) {
                    uint32_t vF[4];
                    ldsm4t(vF, vBase + dj * 32);
                    mma16(O[dj * 2], aP, vF);
                    mma16(O[dj * 2 + 1], aP, vF + 2);
                }
            }
        }
        __syncthreads();
    }

    __half* Yb = Y + ((size_t)(b * 2048 + qb * 64)) * 2048 + h * 128;
    float inv0 = 1.f / l0, inv1 = 1.f / l1;
#pragma unroll
    for (int nf = 0; nf < 16; nf++) {
        int cN = nf * 8 + 2 * t;
        *reinterpret_cast<__half2*>(Yb + (size_t)(w * 16 + g) * 2048 + cN) =
            __floats2half2_rn(O[nf][0] * inv0, O[nf][1] * inv0);
        *reinterpret_cast<__half2*>(Yb + (size_t)(w * 16 + g + 8) * 2048 + cN) =
            __floats2half2_rn(O[nf][2] * inv1, O[nf][3] * inv1);
    }
}

// ---------------------------------------------------------------------------
// Launch
// ---------------------------------------------------------------------------
extern "C" void kernel_launch(void* const* d_in, const int* in_sizes, int n_in,
                              void* d_out, int out_size) {
    (void)in_sizes; (void)n_in; (void)out_size;
    const float* x  = (const float*)d_in[0];
    const float* Wq = (const float*)d_in[1];
    const float* Wk = (const float*)d_in[2];
    const float* Wv = (const float*)d_in[3];
    const float* Wo = (const float*)d_in[4];
    float* out = (float*)d_out;

    __half *xh, *Wf, *Wot, *Cqkv, *AYp;
    cudaGetSymbolAddress((void**)&xh,   g_xh);
    cudaGetSymbolAddress((void**)&Wf,   g_Wf);
    cudaGetSymbolAddress((void**)&Wot,  g_Wot);
    cudaGetSymbolAddress((void**)&Cqkv, g_QKV);
    cudaGetSymbolAddress((void**)&AYp,  g_AYh);

    const int SMEM_GEMM = 8 * 128 * 20 * 4;  // 81920 B (4 stages x A,B)
    cudaFuncSetAttribute(gemm_hh<3072, true>,
                         cudaFuncAttributeMaxDynamicSharedMemorySize, SMEM_GEMM);
    cudaFuncSetAttribute(gemm_hh<2048, false>,
                         cudaFuncAttributeMaxDynamicSharedMemorySize, SMEM_GEMM);
    cudaFuncSetAttribute(attn_f16,
                         cudaFuncAttributeMaxDynamicSharedMemorySize, ATTN_SMEM);

    // Stage 0: prep (x -> half; all 4 weights -> transposed half, one launch)
    f2h_kernel<<<4 * 2048 * 2048 / 1024, 256>>>(x, xh);
    transpose_w4<<<dim3(160, 64), 256>>>(Wq, Wk, Wv, Wo, Wf, Wot);

    // Stage 1: fused QKV projection (M=8192, N=3072, K=2048)
    gemm_hh<3072, true><<<dim3(24, 64), 256, SMEM_GEMM>>>(xh, Wf, Cqkv);

    // Stage 2: causal GQA flash attention (V via ldmatrix.trans, no
    // transpose_v kernel; longest-first CTA order)
    attn_f16<<<dim3(32, 16, 4), 128, ATTN_SMEM>>>(Cqkv, AYp);

    // Stage 3: output projection (M=8192, N=2048), f32 out
    gemm_hh<2048, false><<<dim3(16, 64), 256, SMEM_GEMM>>>(AYp, Wot, out);
}

// round 17
// speedup vs baseline: 1.0827x; 1.0082x over previous
#include <cuda_runtime.h>
#include <cuda_fp16.h>
#include <cstdint>

#define DEV_INLINE __device__ __forceinline__

// ---------------------------------------------------------------------------
// Problem constants: B=4, T=2048, E=2048, H=16, KV=4, G=4, D=128
// Fused QKV width: H*D + 2*KV*D = 3072
// ---------------------------------------------------------------------------

// Scratch (device-global: allocation-free per harness rules)
__device__ __half g_xh  [4 * 2048 * 2048];     // x half             32 MB
__device__ __half g_Wf  [3072 * 2048];         // [Wq;Wk;Wv]^T half  12 MB
__device__ __half g_Wot [2048 * 2048];         // Wo^T half           8 MB
__device__ __half g_QKV [4 * 2048 * 3072];     // fused QKV out      48 MB
__device__ __half g_AYh [4 * 2048 * 2048];     // attn out half      32 MB

DEV_INLINE uint32_t packh2(float lo, float hi) {
    __half2 h = __floats2half2_rn(lo, hi);
    return *reinterpret_cast<uint32_t*>(&h);
}
DEV_INLINE void mma16(float* c, const uint32_t* a, const uint32_t* b) {
    asm("mma.sync.aligned.m16n8k16.row.col.f32.f16.f16.f32 "
        "{%0,%1,%2,%3}, {%4,%5,%6,%7}, {%8,%9}, {%0,%1,%2,%3};"
        : "+f"(c[0]), "+f"(c[1]), "+f"(c[2]), "+f"(c[3])
        : "r"(a[0]), "r"(a[1]), "r"(a[2]), "r"(a[3]), "r"(b[0]), "r"(b[1]));
}
DEV_INLINE uint32_t sptr(const void* p) {
    return (uint32_t)__cvta_generic_to_shared(p);
}
DEV_INLINE void cp16(uint32_t dst, const void* src) {
    asm volatile("cp.async.cg.shared.global [%0], [%1], 16;" ::
                     "r"(dst), "l"(src));
}
DEV_INLINE void ldsm4(uint32_t* r, uint32_t addr) {
    asm volatile("ldmatrix.sync.aligned.m8n8.x4.shared.b16 {%0,%1,%2,%3}, [%4];"
                 : "=r"(r[0]), "=r"(r[1]), "=r"(r[2]), "=r"(r[3])
                 : "r"(addr));
}
DEV_INLINE void ldsm4t(uint32_t* r, uint32_t addr) {
    asm volatile(
        "ldmatrix.sync.aligned.m8n8.x4.trans.shared.b16 {%0,%1,%2,%3}, [%4];"
        : "=r"(r[0]), "=r"(r[1]), "=r"(r[2]), "=r"(r[3])
        : "r"(addr));
}

// ---------------------------------------------------------------------------
// Prep kernels
// ---------------------------------------------------------------------------
__global__ __launch_bounds__(256) void f2h_kernel(const float* __restrict__ in,
                                                  __half* __restrict__ out) {
    int i = (blockIdx.x * 256 + threadIdx.x) * 4;
    float4 v = *(const float4*)(in + i);
    uint2 o;
    o.x = packh2(v.x, v.y);
    o.y = packh2(v.z, v.w);
    *(uint2*)(out + i) = o;
}

// Fused weight transpose: all four W (K=2048, N) f32 -> (N, 2048) half.
// grid (160, 64): bx<64 Wq | <80 Wk | <96 Wv | else Wo. Tile 32x32.
__global__ __launch_bounds__(256) void transpose_w4(
    const float* __restrict__ Wq, const float* __restrict__ Wk,
    const float* __restrict__ Wv, const float* __restrict__ Wo,
    __half* __restrict__ Wf, __half* __restrict__ Wot) {
    __shared__ float t[32][33];
    const int bx = blockIdx.x;
    const float* W;
    __half* Wt;
    int Ncols, n0;
    if (bx < 64) {
        W = Wq; Wt = Wf; Ncols = 2048; n0 = bx * 32;
    } else if (bx < 80) {
        W = Wk; Wt = Wf + (size_t)2048 * 2048; Ncols = 512; n0 = (bx - 64) * 32;
    } else if (bx < 96) {
        W = Wv; Wt = Wf + (size_t)2560 * 2048; Ncols = 512; n0 = (bx - 80) * 32;
    } else {
        W = Wo; Wt = Wot; Ncols = 2048; n0 = (bx - 96) * 32;
    }
    const int k0 = blockIdx.y * 32;
    const int lx = threadIdx.x & 31, ly = threadIdx.x >> 5;
#pragma unroll
    for (int i = 0; i < 4; i++)
        t[ly + 8 * i][lx] = W[(size_t)(k0 + ly + 8 * i) * Ncols + n0 + lx];
    __syncthreads();
#pragma unroll
    for (int i = 0; i < 4; i++)
        Wt[(size_t)(n0 + ly + 8 * i) * 2048 + k0 + lx] =
            __float2half(t[lx][ly + 8 * i]);
}

// ---------------------------------------------------------------------------
// fp16 GEMM: C(MxN) = A(M,K) @ Bt(N,K)^T.
// BM=128 BN=128 BK=32; 256 threads = 8 warps (2m x 4n); warp tile 64x32.
// 4-stage cp.async pipeline (3 tiles in flight), one barrier per iteration,
// ldmatrix fragments. smem rows 20 uint32 (80 B): conflict-free phases.
// (round-13 proven config)
// ---------------------------------------------------------------------------
template <int N, bool HALF_OUT>
__global__ __launch_bounds__(256) void gemm_hh(const __half* __restrict__ A,
                                               const __half* __restrict__ Bt,
                                               void* __restrict__ Cv) {
    constexpr int K = 2048;
    constexpr int NT = K / 32;
    constexpr int STG = 128 * 20;  // uint32 units per stage per operand
    extern __shared__ uint32_t smem[];

    const int tid = threadIdx.x;
    const int lane = tid & 31, wid = tid >> 5;
    const int g = lane >> 2, t = lane & 3;
    const int wm = wid & 1, wn = wid >> 1;
    const int bm = blockIdx.y * 128, bn = blockIdx.x * 128;

    const int l_row = tid >> 1;       // 0..127
    const int l_u0  = (tid & 1) * 8;  // unit 0 or 8

    const __half* gA = A + (size_t)(bm + l_row) * K + 2 * l_u0;
    const __half* gB = Bt + (size_t)(bn + l_row) * K + 2 * l_u0;

    const uint32_t sA = sptr(smem);
    const uint32_t sB = sA + 4 * STG * 4;
    const uint32_t stA = sA + l_row * 80 + l_u0 * 4;
    const uint32_t stB = sB + l_row * 80 + l_u0 * 4;

    const uint32_t aAddr =
        sA + (wm * 64 + (lane & 7) + ((lane >> 3) & 1) * 8) * 80 +
        ((lane >> 4) * 4) * 4;
    const uint32_t bAddr =
        sB + (wn * 32 + (lane & 7) + ((lane >> 4) & 1) * 8) * 80 +
        (((lane >> 3) & 1) * 4) * 4;

    float acc[4][4][4];
#pragma unroll
    for (int mi = 0; mi < 4; mi++)
#pragma unroll
        for (int ni = 0; ni < 4; ni++)
#pragma unroll
            for (int j = 0; j < 4; j++) acc[mi][ni][j] = 0.f;

    auto issue = [&](int kt) {
        const uint32_t off = (kt & 3) * STG * 4;
        const __half* a = gA + kt * 32;
        cp16(stA + off, a);
        cp16(stA + off + 16, a + 8);
        const __half* b = gB + kt * 32;
        cp16(stB + off, b);
        cp16(stB + off + 16, b + 8);
        asm volatile("cp.async.commit_group;" ::: "memory");
    };

    issue(0);
    issue(1);
    issue(2);

    for (int kt = 0; kt < NT; kt++) {
        if (kt < NT - 2)
            asm volatile("cp.async.wait_group 2;" ::: "memory");
        else if (kt == NT - 2)
            asm volatile("cp.async.wait_group 1;" ::: "memory");
        else
            asm volatile("cp.async.wait_group 0;" ::: "memory");
        __syncthreads();
        if (kt + 3 < NT) issue(kt + 3);

        const uint32_t soff = (kt & 3) * STG * 4;
#pragma unroll
        for (int ks = 0; ks < 2; ks++) {
            uint32_t aF[4][4], bF[2][4];
#pragma unroll
            for (int mi = 0; mi < 4; mi++)
                ldsm4(aF[mi], aAddr + soff + mi * 16 * 80 + ks * 32);
            ldsm4(bF[0], bAddr + soff + ks * 32);
            ldsm4(bF[1], bAddr + soff + 16 * 80 + ks * 32);
#pragma unroll
            for (int ni = 0; ni < 4; ni++) {
                const uint32_t* bp = &bF[ni >> 1][(ni & 1) * 2];
#pragma unroll
                for (int mi = 0; mi < 4; mi++) mma16(acc[mi][ni], aF[mi], bp);
            }
        }
    }

    // epilogue
#pragma unroll
    for (int mi = 0; mi < 4; mi++) {
        int r0 = bm + wm * 64 + mi * 16 + g;
#pragma unroll
        for (int ni = 0; ni < 4; ni++) {
            int cN = bn + wn * 32 + ni * 8 + 2 * t;
            if (HALF_OUT) {
                __half* C = (__half*)Cv;
                *reinterpret_cast<__half2*>(C + (size_t)r0 * N + cN) =
                    __floats2half2_rn(acc[mi][ni][0], acc[mi][ni][1]);
                *reinterpret_cast<__half2*>(C + (size_t)(r0 + 8) * N + cN) =
                    __floats2half2_rn(acc[mi][ni][2], acc[mi][ni][3]);
            } else {
                float* C = (float*)Cv;
                *(float2*)(C + (size_t)r0 * N + cN) =
                    make_float2(acc[mi][ni][0], acc[mi][ni][1]);
                *(float2*)(C + (size_t)(r0 + 8) * N + cN) =
                    make_float2(acc[mi][ni][2], acc[mi][ni][3]);
            }
        }
    }
}

// ---------------------------------------------------------------------------
// Flash attention (causal, GQA), fp16 m16n8k16 core, f32 softmax/accum.
// Grid (T/64, H, B), 128 threads = 4 warps; warp owns 16 query rows.
// Double-buffered cp.async K/V tiles; longest-first CTA order (LPT);
// V fragments via ldmatrix.x4.trans on K-major V tiles.
// NEW this round (occupancy push, target 4 CTAs/SM):
//  - P C-fragments reused DIRECTLY as PV A-fragments (FA2 identity):
//    aP = {packh2(s[2k][0..1]), packh2(s[2k][2..3]), packh2(s[2k+1][0..1]),
//    packh2(s[2k+1][2..3])} -> P smem tile, stores, syncwarp, 2 LDSM removed.
//  - Q fragments loaded per-tile via ldmatrix (frees 32 persistent regs);
//    __launch_bounds__(128, 4) caps regs at 128.
// Smem: Qs[0,4352) Ks[4352,+4352) Vk[8704,+4352) = 13056 u = 52224 B.
// Numerics bit-identical per query row.
// ---------------------------------------------------------------------------
static constexpr int QS_U = 0;
static constexpr int KS_U = 4352;
static constexpr int KS_STG = 2176;  // 32*68
static constexpr int VK_U = 8704;
static constexpr int VK_STG = 2176;  // 32*68
static constexpr int ATTN_SMEM = 13056 * 4;  // 52224 B

__global__ __launch_bounds__(128, 4) void attn_f16(
    const __half* __restrict__ Cqkv, __half* __restrict__ Y) {
    extern __shared__ uint32_t dsm[];

    const int b = blockIdx.z, h = blockIdx.y;
    const int qb = gridDim.x - 1 - blockIdx.x;  // longest-first scheduling
    const int kv = h >> 2;
    const int tid = threadIdx.x, w = tid >> 5, lane = tid & 31;
    const int g = lane >> 2, t = lane & 3;
    const float scale = 0.08838834764831845f;

    const uint4* Cv = reinterpret_cast<const uint4*>(Cqkv);
    const uint32_t smb = sptr(dsm);

    const uint32_t qAddr =
        smb + QS_U * 4 +
        (w * 16 + (lane & 7) + ((lane >> 3) & 1) * 8) * 272 +
        ((lane >> 4) * 4) * 4;
    const uint32_t kAddr0 =
        smb + KS_U * 4 + ((lane & 7) + ((lane >> 4) & 1) * 8) * 272 +
        (((lane >> 3) & 1) * 4) * 4;
    // trans V fragment base: row = key = (lane&7) + 8*((lane>>3)&1),
    // col halfs = 8*(lane>>4); per ks2 add 16 rows, per d16-block add 32 B.
    const uint32_t vAddrT0 =
        smb + VK_U * 4 + ((lane & 7) + ((lane >> 3) & 1) * 8) * 272 +
        (lane >> 4) * 16;

    // cp.async loader mapping: 32 rows x 4 col-groups(64B) for K and V
    const int kr = tid >> 2, kc = tid & 3;
    const uint32_t kDst = smb + KS_U * 4 + kr * 272 + kc * 64;
    const uint32_t vDst = smb + VK_U * 4 + kr * 272 + kc * 64;
    const __half* kSrc0 =
        Cqkv + (size_t)(b * 2048 + kr) * 3072 + 2048 + kv * 128 + kc * 32;
    const __half* vSrc0 = kSrc0 + 512;  // V slice sits 512 halfs after K

    // Stage Q block: 64 rows x 16 uint4 (row stride 3072 half = 384 uint4)
    {
        int r = tid >> 1, q = tid & 1;
        size_t base = (size_t)(b * 2048 + qb * 64 + r) * 384 + h * 16;
#pragma unroll
        for (int j = 0; j < 8; j++) {
            uint4 v = Cv[base + q * 8 + j];
            *(uint4*)&dsm[QS_U + r * 68 + (q * 8 + j) * 4] = v;
        }
    }

    const int ntiles = qb * 2 + 2;

    auto issue = [&](int jt) {
        const uint32_t kOff = (jt & 1) * KS_STG * 4;
        const uint32_t vOff = (jt & 1) * VK_STG * 4;
        const __half* ks = kSrc0 + (size_t)(jt * 32) * 3072;
        const __half* vs = vSrc0 + (size_t)(jt * 32) * 3072;
#pragma unroll
        for (int j = 0; j < 4; j++) cp16(kDst + kOff + j * 16, ks + j * 8);
#pragma unroll
        for (int j = 0; j < 4; j++) cp16(vDst + vOff + j * 16, vs + j * 8);
        asm volatile("cp.async.commit_group;" ::: "memory");
    };

    issue(0);
    __syncthreads();  // Q staged (plain stores) visible to all warps

    float O[16][4];
#pragma unroll
    for (int i = 0; i < 16; i++)
#pragma unroll
        for (int j = 0; j < 4; j++) O[i][j] = 0.f;
    float m0 = -1e30f, m1 = -1e30f, l0 = 0.f, l1 = 0.f;

    const int qr0 = qb * 64 + w * 16 + g;
    const int qr1 = qr0 + 8;
    const int qmaxw = qb * 64 + w * 16 + 15;

    for (int jt = 0; jt < ntiles; jt++) {
        const int jbase = jt * 32;
        if (jt + 1 < ntiles) issue(jt + 1);
        if (jt + 1 < ntiles)
            asm volatile("cp.async.wait_group 1;" ::: "memory");
        else
            asm volatile("cp.async.wait_group 0;" ::: "memory");
        __syncthreads();

        if (jbase <= qmaxw) {
            const uint32_t kAddr = kAddr0 + (jt & 1) * KS_STG * 4;
            const uint32_t vAddrT = vAddrT0 + (jt & 1) * VK_STG * 4;

            // S = Q @ K^T (16 x 32); Q frags loaded per k16-step (smem-hot)
            float s[4][4];
#pragma unroll
            for (int ni = 0; ni < 4; ni++)
#pragma unroll
                for (int j = 0; j < 4; j++) s[ni][j] = 0.f;
#pragma unroll
            for (int ks = 0; ks < 8; ks++) {
                uint32_t qF[4], kA[4], kB[4];
                ldsm4(qF, qAddr + ks * 32);
                ldsm4(kA, kAddr + ks * 32);
                ldsm4(kB, kAddr + 16 * 272 + ks * 32);
                mma16(s[0], qF, kA);
                mma16(s[1], qF, kA + 2);
                mma16(s[2], qF, kB);
                mma16(s[3], qF, kB + 2);
            }

            // scale + causal mask
#pragma unroll
            for (int ni = 0; ni < 4; ni++) {
                int col = jbase + ni * 8 + 2 * t;
                s[ni][0] = (col     <= qr0) ? s[ni][0] * scale : -1e30f;
                s[ni][1] = (col + 1 <= qr0) ? s[ni][1] * scale : -1e30f;
                s[ni][2] = (col     <= qr1) ? s[ni][2] * scale : -1e30f;
                s[ni][3] = (col + 1 <= qr1) ? s[ni][3] * scale : -1e30f;
            }

            // online softmax row statistics
            float tm0 = -1e30f, tm1 = -1e30f;
#pragma unroll
            for (int ni = 0; ni < 4; ni++) {
                tm0 = fmaxf(tm0, fmaxf(s[ni][0], s[ni][1]));
                tm1 = fmaxf(tm1, fmaxf(s[ni][2], s[ni][3]));
            }
            tm0 = fmaxf(tm0, __shfl_xor_sync(0xffffffffu, tm0, 1));
            tm0 = fmaxf(tm0, __shfl_xor_sync(0xffffffffu, tm0, 2));
            tm1 = fmaxf(tm1, __shfl_xor_sync(0xffffffffu, tm1, 1));
            tm1 = fmaxf(tm1, __shfl_xor_sync(0xffffffffu, tm1, 2));
            float nm0 = fmaxf(m0, tm0), nm1 = fmaxf(m1, tm1);
            float corr0 = __expf(m0 - nm0), corr1 = __expf(m1 - nm1);

            float ls0 = 0.f, ls1 = 0.f;
#pragma unroll
            for (int ni = 0; ni < 4; ni++) {
                s[ni][0] = __expf(s[ni][0] - nm0);
                s[ni][1] = __expf(s[ni][1] - nm0);
                s[ni][2] = __expf(s[ni][2] - nm1);
                s[ni][3] = __expf(s[ni][3] - nm1);
                ls0 += s[ni][0] + s[ni][1];
                ls1 += s[ni][2] + s[ni][3];
            }
            ls0 += __shfl_xor_sync(0xffffffffu, ls0, 1);
            ls0 += __shfl_xor_sync(0xffffffffu, ls0, 2);
            ls1 += __shfl_xor_sync(0xffffffffu, ls1, 1);
            ls1 += __shfl_xor_sync(0xffffffffu, ls1, 2);
            l0 = l0 * corr0 + ls0;
            l1 = l1 * corr1 + ls1;
            m0 = nm0;
            m1 = nm1;

            // rescale O accumulator
#pragma unroll
            for (int nf = 0; nf < 16; nf++) {
                O[nf][0] *= corr0; O[nf][1] *= corr0;
                O[nf][2] *= corr1; O[nf][3] *= corr1;
            }

            // O += P @ V : P C-frags map DIRECTLY to A-frags (no smem trip);
            // V frags via ldmatrix.trans on the K-major V tile.
#pragma unroll
            for (int ks2 = 0; ks2 < 2; ks2++) {
                uint32_t aP[4];
                aP[0] = packh2(s[2 * ks2][0], s[2 * ks2][1]);
                aP[1] = packh2(s[2 * ks2][2], s[2 * ks2][3]);
                aP[2] = packh2(s[2 * ks2 + 1][0], s[2 * ks2 + 1][1]);
                aP[3] = packh2(s[2 * ks2 + 1][2], s[2 * ks2 + 1][3]);
                const uint32_t vBase = vAddrT + ks2 * 16 * 272;
#pragma unroll
                for (int dj = 0; dj < 8; dj++) {
                    uint32_t vF[4];
                    ldsm4t(vF, vBase + dj * 32);
                    mma16(O[dj * 2], aP, vF);
                    mma16(O[dj * 2 + 1], aP, vF + 2);
                }
            }
        }
        __syncthreads();
    }

    __half* Yb = Y + ((size_t)(b * 2048 + qb * 64)) * 2048 + h * 128;
    float inv0 = 1.f / l0, inv1 = 1.f / l1;
#pragma unroll
    for (int nf = 0; nf < 16; nf++) {
        int cN = nf * 8 + 2 * t;
        *reinterpret_cast<__half2*>(Yb + (size_t)(w * 16 + g) * 2048 + cN) =
            __floats2half2_rn(O[nf][0] * inv0, O[nf][1] * inv0);
        *reinterpret_cast<__half2*>(Yb + (size_t)(w * 16 + g + 8) * 2048 + cN) =
            __floats2half2_rn(O[nf][2] * inv1, O[nf][3] * inv1);
    }
}

// ---------------------------------------------------------------------------
// Launch
// ---------------------------------------------------------------------------
extern "C" void kernel_launch(void* const* d_in, const int* in_sizes, int n_in,
                              void* d_out, int out_size) {
    (void)in_sizes; (void)n_in; (void)out_size;
    const float* x  = (const float*)d_in[0];
    const float* Wq = (const float*)d_in[1];
    const float* Wk = (const float*)d_in[2];
    const float* Wv = (const float*)d_in[3];
    const float* Wo = (const float*)d_in[4];
    float* out = (float*)d_out;

    __half *xh, *Wf, *Wot, *Cqkv, *AYp;
    cudaGetSymbolAddress((void**)&xh,   g_xh);
    cudaGetSymbolAddress((void**)&Wf,   g_Wf);
    cudaGetSymbolAddress((void**)&Wot,  g_Wot);
    cudaGetSymbolAddress((void**)&Cqkv, g_QKV);
    cudaGetSymbolAddress((void**)&AYp,  g_AYh);

    const int SMEM_GEMM = 8 * 128 * 20 * 4;  // 81920 B (4 stages x A,B)
    cudaFuncSetAttribute(gemm_hh<3072, true>,
                         cudaFuncAttributeMaxDynamicSharedMemorySize, SMEM_GEMM);
    cudaFuncSetAttribute(gemm_hh<2048, false>,
                         cudaFuncAttributeMaxDynamicSharedMemorySize, SMEM_GEMM);
    cudaFuncSetAttribute(attn_f16,
                         cudaFuncAttributeMaxDynamicSharedMemorySize, ATTN_SMEM);

    // Stage 0: prep (x -> half; all 4 weights -> transposed half, one launch)
    f2h_kernel<<<4 * 2048 * 2048 / 1024, 256>>>(x, xh);
    transpose_w4<<<dim3(160, 64), 256>>>(Wq, Wk, Wv, Wo, Wf, Wot);

    // Stage 1: fused QKV projection (M=8192, N=3072, K=2048)
    gemm_hh<3072, true><<<dim3(24, 64), 256, SMEM_GEMM>>>(xh, Wf, Cqkv);

    // Stage 2: causal GQA flash attention (P-frag direct reuse, per-tile Q
    // ldmatrix, 4 CTAs/SM target; longest-first CTA order)
    attn_f16<<<dim3(32, 16, 4), 128, ATTN_SMEM>>>(Cqkv, AYp);

    // Stage 3: output projection (M=8192, N=2048), f32 out
    gemm_hh<2048, false><<<dim3(16, 64), 256, SMEM_GEMM>>>(AYp, Wot, out);
}